// round 14
// baseline (speedup 1.0000x reference)
#include <cuda_runtime.h>

#define BATCH 16
#define HDIM 512
#define WDIM 512
#define HW (HDIM * WDIM)
#define NTOT (BATCH * 3 * HW)
#define STRIPS_TOT (BATCH * 256)   // 2-row strips, 4096 total
#define GRID 592                   // 148 SMs x 4 blocks -> single wave
#define THREADS 256

__device__ double       g_acc;
__device__ unsigned int g_count;

__global__ void __launch_bounds__(THREADS, 4)
fused_loss_kernel(const float* __restrict__ pred,
                  const float* __restrict__ targ,
                  const int*   __restrict__ lm,
                  float*       __restrict__ out) {
    __shared__ float    scx[BATCH * 32];
    __shared__ float    scy[BATCH * 32];
    __shared__ unsigned s_maskArr[8];     // per-iteration landmark masks
    __shared__ float    s_warp[8];

    const int t   = threadIdx.x;
    const int bid = blockIdx.x;
    const int nIter = (STRIPS_TOT - bid + GRID - 1) / GRID;   // 6 or 7

    // ---- Load ALL landmarks (16 batches x 32) into smem: one int2 each ----
    for (int i = t; i < BATCH * 32; i += THREADS) {      // 2 iterations
        const int b = i >> 5, j = i & 31;
        const int2 c = __ldg(reinterpret_cast<const int2*>(lm) + (b * 68 + 36 + j));
        scx[i] = fminf(fmaxf((float)c.x, 0.f), (float)(WDIM - 1));
        scy[i] = fminf(fmaxf((float)c.y, 0.f), (float)(HDIM - 1));
    }
    __syncthreads();

    // ---- Precompute ALL iteration masks (warp 0), then one barrier ----
    if (t < 32) {
        for (int it = 0; it < nIter; ++it) {
            const int sid = bid + it * GRID;
            const int b   = sid >> 8;
            const float y0 = (float)((sid & 255) << 1);
            const float cy = scy[(b << 5) + t];
            const bool hit = (cy >= y0 - 15.f) && (cy <= y0 + 16.f);
            const unsigned m = __ballot_sync(0xffffffffu, hit);
            if (t == 0) s_maskArr[it] = m;
        }
    }
    __syncthreads();

    // Thread -> (row 0/1 of strip, one quad). 128 threads per 512-px row.
    const int   row = t >> 7;
    const int   xq  = (t & 127) << 2;
    const float xf  = (float)xq;

    float a0 = 0.f, a1 = 0.f, a2 = 0.f, a3 = 0.f;

    // ---- Main loop: NO barriers, NO ballots, NO shared writes ----
    for (int it = 0; it < nIter; ++it) {
        const int sid = bid + it * GRID;
        const int b   = sid >> 8;
        const int y   = ((sid & 255) << 1) + row;
        const float yf = (float)y;

        // Issue all 6 float4 pairs for this iteration immediately.
        const float4* pp = reinterpret_cast<const float4*>(pred + b * 3 * HW + y * WDIM + xq);
        const float4* qq = reinterpret_cast<const float4*>(targ + b * 3 * HW + y * WDIM + xq);
        const float4 p0 = pp[0];          const float4 q0 = qq[0];
        const float4 p1 = pp[HW / 4];     const float4 q1 = qq[HW / 4];
        const float4 p2 = pp[HW / 2];     const float4 q2 = qq[HW / 2];

        // Weights (block-uniform branch; ~2 landmarks avg when taken).
        float w0 = 1.f, w1 = 1.f, w2 = 1.f, w3 = 1.f;
        unsigned m = s_maskArr[it];
        if (m) {
            float e0 = 0.f, e1 = 0.f, e2 = 0.f, e3 = 0.f;
            float f0 = 0.f, f1 = 0.f, f2 = 0.f, f3 = 0.f;
            do {
                const int j = __ffs(m) - 1;
                m &= m - 1;
                const float cx = scx[(b << 5) + j];
                const float cy = scy[(b << 5) + j];
                const float dy  = yf - cy;
                const float dy2 = dy * dy;
                if (dy2 < 225.f && fabsf(xf + 1.5f - cx) < 18.f) {
                    const float dx0 = xf - cx;
                    const float dx1 = dx0 + 1.f, dx2 = dx0 + 2.f, dx3 = dx0 + 3.f;
                    const float v0 = 1.f - sqrtf(fmaf(dx0, dx0, dy2)) * (1.f / 15.f);
                    const float v1 = 1.f - sqrtf(fmaf(dx1, dx1, dy2)) * (1.f / 15.f);
                    const float v2 = 1.f - sqrtf(fmaf(dx2, dx2, dy2)) * (1.f / 15.f);
                    const float v3 = 1.f - sqrtf(fmaf(dx3, dx3, dy2)) * (1.f / 15.f);
                    if (j < 12) {
                        e0 = fmaxf(e0, v0); e1 = fmaxf(e1, v1);
                        e2 = fmaxf(e2, v2); e3 = fmaxf(e3, v3);
                    } else {
                        f0 = fmaxf(f0, v0); f1 = fmaxf(f1, v1);
                        f2 = fmaxf(f2, v2); f3 = fmaxf(f3, v3);
                    }
                }
            } while (m);
            w0 = fmaf(fminf(e0 + f0, 1.f), 299.f, 1.f);
            w1 = fmaf(fminf(e1 + f1, 1.f), 299.f, 1.f);
            w2 = fmaf(fminf(e2 + f2, 1.f), 299.f, 1.f);
            w3 = fmaf(fminf(e3 + f3, 1.f), 299.f, 1.f);
        }

        // Consume with 4 independent accumulator chains.
        a0 += w0 * fabsf(p0.x - q0.x);
        a1 += w1 * fabsf(p0.y - q0.y);
        a2 += w2 * fabsf(p0.z - q0.z);
        a3 += w3 * fabsf(p0.w - q0.w);
        a0 += w0 * fabsf(p1.x - q1.x);
        a1 += w1 * fabsf(p1.y - q1.y);
        a2 += w2 * fabsf(p1.z - q1.z);
        a3 += w3 * fabsf(p1.w - q1.w);
        a0 += w0 * fabsf(p2.x - q2.x);
        a1 += w1 * fabsf(p2.y - q2.y);
        a2 += w2 * fabsf(p2.z - q2.z);
        a3 += w3 * fabsf(p2.w - q2.w);
    }

    float acc = (a0 + a1) + (a2 + a3);

    // ---- Block reduction (8 warps) + device-side finalize ----
    #pragma unroll
    for (int off = 16; off; off >>= 1)
        acc += __shfl_down_sync(0xffffffffu, acc, off);

    const int lane32 = t & 31, wid = t >> 5;
    if (lane32 == 0) s_warp[wid] = acc;
    __syncthreads();
    if (wid == 0) {
        acc = (lane32 < 8) ? s_warp[lane32] : 0.0f;
        #pragma unroll
        for (int off = 4; off; off >>= 1)
            acc += __shfl_down_sync(0xffffffffu, acc, off);

        if (lane32 == 0) {
            atomicAdd(&g_acc, (double)acc);
            __threadfence();
            unsigned int ticket = atomicAdd(&g_count, 1u);
            if (ticket == GRID - 1) {
                __threadfence();
                double total = *((volatile double*)&g_acc);
                out[0] = (float)(total * (1.0 / (double)NTOT));
                g_acc   = 0.0;          // clean state for next graph replay
                g_count = 0u;
            }
        }
    }
}

extern "C" void kernel_launch(void* const* d_in, const int* in_sizes, int n_in,
                              void* d_out, int out_size) {
    const float* pred = (const float*)d_in[0];
    const float* targ = (const float*)d_in[1];
    const int*   lm   = (const int*)d_in[2];
    float*       out  = (float*)d_out;

    fused_loss_kernel<<<GRID, THREADS>>>(pred, targ, lm, out);
}

// round 16
// speedup vs baseline: 1.1078x; 1.1078x over previous
#include <cuda_runtime.h>

#define BATCH 16
#define HDIM 512
#define WDIM 512
#define HW (HDIM * WDIM)
#define NTOT (BATCH * 3 * HW)
#define STRIPS_TOT (BATCH * 256)   // 2-row strips, 4096 total
#define GRID 592                   // 148 SMs x 4 blocks -> single wave
#define THREADS 256

__device__ double       g_acc;
__device__ unsigned int g_count;

__global__ void __launch_bounds__(THREADS, 4)
fused_loss_kernel(const float* __restrict__ pred,
                  const float* __restrict__ targ,
                  const int*   __restrict__ lm,
                  float*       __restrict__ out) {
    __shared__ float    scx[BATCH * 32];
    __shared__ float    scy[BATCH * 32];
    __shared__ unsigned s_maskArr[8];     // per-iteration landmark masks
    __shared__ float    s_warp[8];

    const int t   = threadIdx.x;
    const int bid = blockIdx.x;
    const int nIter = (STRIPS_TOT - bid + GRID - 1) / GRID;   // 6 or 7

    // ---- Load ALL landmarks (16 batches x 32) into smem once ----
    for (int i = t; i < BATCH * 32; i += THREADS) {
        const int b = i >> 5, j = i & 31;
        int cx = lm[(b * 68 + 36 + j) * 2 + 0];
        int cy = lm[(b * 68 + 36 + j) * 2 + 1];
        scx[i] = (float)min(max(cx, 0), WDIM - 1);
        scy[i] = (float)min(max(cy, 0), HDIM - 1);
    }
    __syncthreads();

    // ---- Precompute ALL iteration masks (warp 0), then one barrier ----
    if (t < 32) {
        for (int it = 0; it < nIter; ++it) {
            const int sid = bid + it * GRID;
            const int b   = sid >> 8;
            const float y0 = (float)((sid & 255) << 1);
            const float cy = scy[(b << 5) + t];
            const bool hit = (cy >= y0 - 15.f) && (cy <= y0 + 16.f);
            const unsigned m = __ballot_sync(0xffffffffu, hit);
            if (t == 0) s_maskArr[it] = m;
        }
    }
    __syncthreads();

    // Thread -> (row 0/1 of strip, one quad). 128 threads per 512-px row.
    const int   row = t >> 7;
    const int   xq  = (t & 127) << 2;
    const float xf  = (float)xq;

    float a0 = 0.f, a1 = 0.f, a2 = 0.f, a3 = 0.f;

    // ---- Main loop: NO barriers, NO ballots, NO shared writes ----
    for (int it = 0; it < nIter; ++it) {
        const int sid = bid + it * GRID;
        const int b   = sid >> 8;
        const int y   = ((sid & 255) << 1) + row;
        const float yf = (float)y;

        // Issue all 6 float4 pairs for this iteration immediately.
        const float4* pp = reinterpret_cast<const float4*>(pred + b * 3 * HW + y * WDIM + xq);
        const float4* qq = reinterpret_cast<const float4*>(targ + b * 3 * HW + y * WDIM + xq);
        const float4 p0 = pp[0];          const float4 q0 = qq[0];
        const float4 p1 = pp[HW / 4];     const float4 q1 = qq[HW / 4];
        const float4 p2 = pp[HW / 2];     const float4 q2 = qq[HW / 2];

        // Weights (block-uniform branch; ~2 landmarks avg when taken).
        float w0 = 1.f, w1 = 1.f, w2 = 1.f, w3 = 1.f;
        unsigned m = s_maskArr[it];
        if (m) {
            float e0 = 0.f, e1 = 0.f, e2 = 0.f, e3 = 0.f;
            float f0 = 0.f, f1 = 0.f, f2 = 0.f, f3 = 0.f;
            do {
                const int j = __ffs(m) - 1;
                m &= m - 1;
                const float cx = scx[(b << 5) + j];
                const float cy = scy[(b << 5) + j];
                const float dy  = yf - cy;
                const float dy2 = dy * dy;
                if (dy2 < 225.f && fabsf(xf + 1.5f - cx) < 18.f) {
                    const float dx0 = xf - cx;
                    const float dx1 = dx0 + 1.f, dx2 = dx0 + 2.f, dx3 = dx0 + 3.f;
                    const float v0 = 1.f - sqrtf(fmaf(dx0, dx0, dy2)) * (1.f / 15.f);
                    const float v1 = 1.f - sqrtf(fmaf(dx1, dx1, dy2)) * (1.f / 15.f);
                    const float v2 = 1.f - sqrtf(fmaf(dx2, dx2, dy2)) * (1.f / 15.f);
                    const float v3 = 1.f - sqrtf(fmaf(dx3, dx3, dy2)) * (1.f / 15.f);
                    if (j < 12) {
                        e0 = fmaxf(e0, v0); e1 = fmaxf(e1, v1);
                        e2 = fmaxf(e2, v2); e3 = fmaxf(e3, v3);
                    } else {
                        f0 = fmaxf(f0, v0); f1 = fmaxf(f1, v1);
                        f2 = fmaxf(f2, v2); f3 = fmaxf(f3, v3);
                    }
                }
            } while (m);
            w0 = fmaf(fminf(e0 + f0, 1.f), 299.f, 1.f);
            w1 = fmaf(fminf(e1 + f1, 1.f), 299.f, 1.f);
            w2 = fmaf(fminf(e2 + f2, 1.f), 299.f, 1.f);
            w3 = fmaf(fminf(e3 + f3, 1.f), 299.f, 1.f);
        }

        // Consume with 4 independent accumulator chains.
        a0 += w0 * fabsf(p0.x - q0.x);
        a1 += w1 * fabsf(p0.y - q0.y);
        a2 += w2 * fabsf(p0.z - q0.z);
        a3 += w3 * fabsf(p0.w - q0.w);
        a0 += w0 * fabsf(p1.x - q1.x);
        a1 += w1 * fabsf(p1.y - q1.y);
        a2 += w2 * fabsf(p1.z - q1.z);
        a3 += w3 * fabsf(p1.w - q1.w);
        a0 += w0 * fabsf(p2.x - q2.x);
        a1 += w1 * fabsf(p2.y - q2.y);
        a2 += w2 * fabsf(p2.z - q2.z);
        a3 += w3 * fabsf(p2.w - q2.w);
    }

    float acc = (a0 + a1) + (a2 + a3);

    // ---- Block reduction (8 warps) + device-side finalize ----
    #pragma unroll
    for (int off = 16; off; off >>= 1)
        acc += __shfl_down_sync(0xffffffffu, acc, off);

    const int lane32 = t & 31, wid = t >> 5;
    if (lane32 == 0) s_warp[wid] = acc;
    __syncthreads();
    if (wid == 0) {
        acc = (lane32 < 8) ? s_warp[lane32] : 0.0f;
        #pragma unroll
        for (int off = 4; off; off >>= 1)
            acc += __shfl_down_sync(0xffffffffu, acc, off);

        if (lane32 == 0) {
            atomicAdd(&g_acc, (double)acc);
            __threadfence();
            unsigned int ticket = atomicAdd(&g_count, 1u);
            if (ticket == GRID - 1) {
                __threadfence();
                double total = *((volatile double*)&g_acc);
                out[0] = (float)(total * (1.0 / (double)NTOT));
                g_acc   = 0.0;          // clean state for next graph replay
                g_count = 0u;
            }
        }
    }
}

extern "C" void kernel_launch(void* const* d_in, const int* in_sizes, int n_in,
                              void* d_out, int out_size) {
    const float* pred = (const float*)d_in[0];
    const float* targ = (const float*)d_in[1];
    const int*   lm   = (const int*)d_in[2];
    float*       out  = (float*)d_out;

    fused_loss_kernel<<<GRID, THREADS>>>(pred, targ, lm, out);
}